// round 6
// baseline (speedup 1.0000x reference)
#include <cuda_runtime.h>

// Problem constants
#define B_ROWS 16
#define NCOL 2048
#define M 4096          // flat rows
#define D 8
#define NC 65536
#define ROWS_PER_M 256  // flat rows per batch row

// Argmin tunables
#define R_PER_THREAD 2
#define NWARPS 8
#define ROWS_PER_BLOCK (NWARPS * R_PER_THREAD)   // 16
#define NSEG 8
#define SEG_CODES (NC / NSEG)                    // 8192
#define TILE 512                                 // codes per shared tile
#define TILE2 (TILE / 2)                         // 256 code-pairs = blockDim
#define NTILES (SEG_CODES / TILE)                // 16

typedef unsigned long long ull;

// Scratch
__device__ float g_scale[B_ROWS];
__device__ float g_cnorm[NC];
__device__ float4 g_cbi[4][NC / 2];  // interleaved code-pair planes
__device__ float2 g_cni[NC / 2];     // norms per pair
__device__ ull   g_key[M];           // (monotone dist bits << 32) | tileId
__device__ int   g_idx[M];
__device__ float g_sums[NC * D];
__device__ float g_counts[NC];

__device__ __forceinline__ ull pack2(float lo, float hi) {
    ull r;
    asm("mov.b64 %0, {%1, %2};" : "=l"(r) : "f"(lo), "f"(hi));
    return r;
}
__device__ __forceinline__ void unpack2(ull v, float& lo, float& hi) {
    asm("mov.b64 {%0, %1}, %2;" : "=f"(lo), "=f"(hi) : "l"(v));
}
__device__ __forceinline__ void fma2(ull& d, ull a, ull b) {
    asm("fma.rn.f32x2 %0, %1, %2, %3;" : "=l"(d) : "l"(a), "l"(b), "l"(d));
}
__device__ __forceinline__ unsigned smem_u32(const void* p) {
    return (unsigned)__cvta_generic_to_shared(p);
}
__device__ __forceinline__ void cpa16(unsigned dst, const void* src) {
    asm volatile("cp.async.cg.shared.global [%0], [%1], 16;" :: "r"(dst), "l"(src));
}
__device__ __forceinline__ void cpa8(unsigned dst, const void* src) {
    asm volatile("cp.async.ca.shared.global [%0], [%1], 8;" :: "r"(dst), "l"(src));
}
__device__ __forceinline__ void cpa_commit() {
    asm volatile("cp.async.commit_group;");
}
template <int N>
__device__ __forceinline__ void cpa_wait() {
    asm volatile("cp.async.wait_group %0;" :: "n"(N));
}

// ---------------------------------------------------------------------------
// Fused prologue: zero sums/counts, init keys, interleave codebook, and
// (blocks 0..15) per-batch-row scale. Grid = (NC*D/256) x 256 threads.
// ---------------------------------------------------------------------------
__global__ void k_pre(const float* __restrict__ x, const float* __restrict__ cb) {
    int t = blockIdx.x * blockDim.x + threadIdx.x;

    g_sums[t] = 0.f;                       // grid covers exactly NC*D
    if (t < NC) g_counts[t] = 0.f;
    if (t < M) g_key[t] = 0xFFFFFFFFFFFFFFFFull;

    if (t < NC / 2) {
        int p = t;
        const float4* cbv = (const float4*)cb;
        float4 a0 = cbv[4 * p + 0], a1 = cbv[4 * p + 1];
        float4 b0 = cbv[4 * p + 2], b1 = cbv[4 * p + 3];
        g_cbi[0][p] = make_float4(a0.x, b0.x, a0.y, b0.y);
        g_cbi[1][p] = make_float4(a0.z, b0.z, a0.w, b0.w);
        g_cbi[2][p] = make_float4(a1.x, b1.x, a1.y, b1.y);
        g_cbi[3][p] = make_float4(a1.z, b1.z, a1.w, b1.w);
        float na = a0.x * a0.x + a0.y * a0.y + a0.z * a0.z + a0.w * a0.w +
                   a1.x * a1.x + a1.y * a1.y + a1.z * a1.z + a1.w * a1.w;
        float nb = b0.x * b0.x + b0.y * b0.y + b0.z * b0.z + b0.w * b0.w +
                   b1.x * b1.x + b1.y * b1.y + b1.z * b1.z + b1.w * b1.w;
        g_cni[p] = make_float2(na, nb);
        g_cnorm[2 * p] = na;
        g_cnorm[2 * p + 1] = nb;
    }

    if (blockIdx.x < B_ROWS) {
        __shared__ float sh[256];
        const float* row = x + blockIdx.x * NCOL;
        float s = 0.f;
        for (int i = threadIdx.x; i < NCOL; i += blockDim.x) s += fabsf(row[i]);
        sh[threadIdx.x] = s;
        __syncthreads();
        for (int off = 128; off > 0; off >>= 1) {
            if (threadIdx.x < off) sh[threadIdx.x] += sh[threadIdx.x + off];
            __syncthreads();
        }
        if (threadIdx.x == 0) g_scale[blockIdx.x] = sh[0] * (1.0f / NCOL);
    }
}

// ---------------------------------------------------------------------------
// Pass 1: per-row min distance + winning 512-code tile. R=2 rows/thread for
// 3 blocks/SM occupancy. Double-buffered cp.async staging.
// ---------------------------------------------------------------------------
__global__ void __launch_bounds__(256, 3) k_argmin(const float* __restrict__ x) {
    __shared__ float4 sh4[2][4][TILE2];   // 32 KB
    __shared__ float2 shcn[2][TILE2];     // 4 KB

    int row0 = blockIdx.x * ROWS_PER_BLOCK;
    int segBase = blockIdx.y * SEG_CODES;
    int ct = threadIdx.x & 31;
    int w = threadIdx.x >> 5;
    int myrow0 = row0 + w * R_PER_THREAD;
    int tid = threadIdx.x;

    ull f2[R_PER_THREAD][D];
#pragma unroll
    for (int r = 0; r < R_PER_THREAD; r++) {
        int m = myrow0 + r;
        float c0 = -2.0f / g_scale[m / ROWS_PER_M];
        const float4* xr = (const float4*)(x + m * D);
        float4 a = xr[0], b = xr[1];
        f2[r][0] = pack2(a.x * c0, a.x * c0);
        f2[r][1] = pack2(a.y * c0, a.y * c0);
        f2[r][2] = pack2(a.z * c0, a.z * c0);
        f2[r][3] = pack2(a.w * c0, a.w * c0);
        f2[r][4] = pack2(b.x * c0, b.x * c0);
        f2[r][5] = pack2(b.y * c0, b.y * c0);
        f2[r][6] = pack2(b.z * c0, b.z * c0);
        f2[r][7] = pack2(b.w * c0, b.w * c0);
    }

    float bestV[R_PER_THREAD];
    int bestT[R_PER_THREAD];
#pragma unroll
    for (int r = 0; r < R_PER_THREAD; r++) { bestV[r] = 3.4e38f; bestT[r] = 0; }

    int pairBase0 = segBase >> 1;
    {
#pragma unroll
        for (int rec = 0; rec < 4; rec++)
            cpa16(smem_u32(&sh4[0][rec][tid]), &g_cbi[rec][pairBase0 + tid]);
        cpa8(smem_u32(&shcn[0][tid]), &g_cni[pairBase0 + tid]);
        cpa_commit();
    }

    for (int t = 0; t < NTILES; t++) {
        int b = t & 1;
        if (t > 0) __syncthreads();
        if (t + 1 < NTILES) {
            int pb = pairBase0 + (t + 1) * TILE2;
#pragma unroll
            for (int rec = 0; rec < 4; rec++)
                cpa16(smem_u32(&sh4[b ^ 1][rec][tid]), &g_cbi[rec][pb + tid]);
            cpa8(smem_u32(&shcn[b ^ 1][tid]), &g_cni[pb + tid]);
            cpa_commit();
            cpa_wait<1>();
        } else {
            cpa_wait<0>();
        }
        __syncthreads();

        float pl[R_PER_THREAD], ph[R_PER_THREAD];
#pragma unroll
        for (int r = 0; r < R_PER_THREAD; r++) { pl[r] = 3.4e38f; ph[r] = 3.4e38f; }

#pragma unroll 4
        for (int i = 0; i < TILE2 / 32; i++) {
            int c2 = ct + 32 * i;
            ulonglong2 q0 = *(const ulonglong2*)&sh4[b][0][c2];
            ulonglong2 q1 = *(const ulonglong2*)&sh4[b][1][c2];
            ulonglong2 q2 = *(const ulonglong2*)&sh4[b][2][c2];
            ulonglong2 q3 = *(const ulonglong2*)&sh4[b][3][c2];
            ull cn2 = *(const ull*)&shcn[b][c2];
#pragma unroll
            for (int r = 0; r < R_PER_THREAD; r++) {
                ull d = cn2;
                fma2(d, f2[r][0], q0.x);
                fma2(d, f2[r][1], q0.y);
                fma2(d, f2[r][2], q1.x);
                fma2(d, f2[r][3], q1.y);
                fma2(d, f2[r][4], q2.x);
                fma2(d, f2[r][5], q2.y);
                fma2(d, f2[r][6], q3.x);
                fma2(d, f2[r][7], q3.y);
                float de, dodd;
                unpack2(d, de, dodd);
                pl[r] = fminf(pl[r], de);
                ph[r] = fminf(ph[r], dodd);
            }
        }

        int tileId = (segBase >> 9) + t;
#pragma unroll
        for (int r = 0; r < R_PER_THREAD; r++) {
            float tmin = fminf(pl[r], ph[r]);
            if (tmin < bestV[r]) { bestV[r] = tmin; bestT[r] = tileId; }
        }
    }

#pragma unroll
    for (int r = 0; r < R_PER_THREAD; r++) {
        float d = bestV[r];
        int t = bestT[r];
        for (int off = 16; off > 0; off >>= 1) {
            float d2 = __shfl_down_sync(0xffffffffu, d, off);
            int t2 = __shfl_down_sync(0xffffffffu, t, off);
            if (d2 < d || (d2 == d && t2 < t)) { d = d2; t = t2; }
        }
        if (ct == 0) {
            unsigned int ud = __float_as_uint(d);
            ud = (ud & 0x80000000u) ? ~ud : (ud | 0x80000000u);
            ull key = ((ull)ud << 32) | (unsigned int)t;
            atomicMin(&g_key[myrow0 + r], key);
        }
    }
}

// ---------------------------------------------------------------------------
// Pass 2 (fused resolve + scatter): one warp per row rescans its winning
// tile with the bit-identical fma2 chain; first matching index wins. Then
// the warp scatters count + 8 dim-sums.
// ---------------------------------------------------------------------------
__global__ void __launch_bounds__(256) k_resolve(const float* __restrict__ x,
                                                 const float* __restrict__ cb) {
    int m = blockIdx.x * (blockDim.x >> 5) + (threadIdx.x >> 5);
    int lane = threadIdx.x & 31;
    if (m >= M) return;

    ull key = g_key[m];
    int tile = (int)(key & 0xFFFFFFFFu);
    unsigned int ud = (unsigned int)(key >> 32);
    ud = (ud & 0x80000000u) ? (ud & 0x7FFFFFFFu) : ~ud;
    float target = __uint_as_float(ud);

    float inv = 1.0f / g_scale[m / ROWS_PER_M];
    float c0 = -2.0f * inv;
    const float4* xr = (const float4*)(x + m * D);
    float4 a = xr[0], b = xr[1];
    ull f2r[D];
    f2r[0] = pack2(a.x * c0, a.x * c0);
    f2r[1] = pack2(a.y * c0, a.y * c0);
    f2r[2] = pack2(a.z * c0, a.z * c0);
    f2r[3] = pack2(a.w * c0, a.w * c0);
    f2r[4] = pack2(b.x * c0, b.x * c0);
    f2r[5] = pack2(b.y * c0, b.y * c0);
    f2r[6] = pack2(b.z * c0, b.z * c0);
    f2r[7] = pack2(b.w * c0, b.w * c0);

    const float4* cbv = (const float4*)cb;
    int base = tile * TILE;
    int best = 0x7FFFFFFF;

#pragma unroll
    for (int p = 0; p < TILE2 / 32; p++) {
        int c2 = lane + 32 * p;
        int code0 = base + 2 * c2;
        float4 a0 = cbv[code0 * 2 + 0];
        float4 a1 = cbv[code0 * 2 + 1];
        float4 b0 = cbv[code0 * 2 + 2];
        float4 b1 = cbv[code0 * 2 + 3];
        ull d = pack2(g_cnorm[code0], g_cnorm[code0 + 1]);
        fma2(d, f2r[0], pack2(a0.x, b0.x));
        fma2(d, f2r[1], pack2(a0.y, b0.y));
        fma2(d, f2r[2], pack2(a0.z, b0.z));
        fma2(d, f2r[3], pack2(a0.w, b0.w));
        fma2(d, f2r[4], pack2(a1.x, b1.x));
        fma2(d, f2r[5], pack2(a1.y, b1.y));
        fma2(d, f2r[6], pack2(a1.z, b1.z));
        fma2(d, f2r[7], pack2(a1.w, b1.w));
        float de, dodd;
        unpack2(d, de, dodd);
        if (de == target) best = min(best, code0);
        else if (dodd == target) best = min(best, code0 + 1);
    }

    for (int off = 16; off > 0; off >>= 1)
        best = min(best, __shfl_xor_sync(0xffffffffu, best, off));

    if (lane == 0) {
        g_idx[m] = best;
        atomicAdd(&g_counts[best], 1.f);
    }
    if (lane < D) {
        float v = x[m * D + lane] * inv;
        atomicAdd(&g_sums[best * D + lane], v);
    }
}

// ---------------------------------------------------------------------------
__global__ void k_gather(float* __restrict__ out) {
    int t = blockIdx.x * blockDim.x + threadIdx.x;
    if (t >= M * D) return;
    int m = t >> 3;
    int j = t & 7;
    int idx = g_idx[m];
    float cnt = g_counts[idx];
    cnt = cnt < 1.f ? 1.f : cnt;
    out[t] = g_scale[m / ROWS_PER_M] * (g_sums[idx * D + j] / cnt);
}

// ---------------------------------------------------------------------------
extern "C" void kernel_launch(void* const* d_in, const int* in_sizes, int n_in,
                              void* d_out, int out_size) {
    const float* x = (const float*)d_in[0];
    const float* cb = (const float*)d_in[1];
    if (n_in >= 2 && in_sizes[0] > in_sizes[1]) {
        x = (const float*)d_in[1];
        cb = (const float*)d_in[0];
    }
    float* out = (float*)d_out;

    k_pre<<<(NC * D) / 256, 256>>>(x, cb);
    dim3 grid(M / ROWS_PER_BLOCK, NSEG);
    k_argmin<<<grid, 256>>>(x);
    k_resolve<<<M / 8, 256>>>(x, cb);
    k_gather<<<(M * D) / 256, 256>>>(out);
}

// round 7
// speedup vs baseline: 1.3996x; 1.3996x over previous
#include <cuda_runtime.h>

// Problem constants
#define B_ROWS 16
#define NCOL 2048
#define M 4096          // flat rows
#define D 8
#define NC 65536
#define ROWS_PER_M 256  // flat rows per batch row

// Argmin tunables (R=4 is the smem-bandwidth/compute balance point)
#define R_PER_THREAD 4
#define NWARPS 8
#define ROWS_PER_BLOCK (NWARPS * R_PER_THREAD)   // 32
#define NSEG 8
#define SEG_CODES (NC / NSEG)                    // 8192
#define TILE 512                                 // codes per shared tile
#define TILE2 (TILE / 2)                         // 256 code-pairs = blockDim
#define NTILES (SEG_CODES / TILE)                // 16

typedef unsigned long long ull;

// Scratch
__device__ float g_scale[B_ROWS];
__device__ float g_cnorm[NC];
__device__ float4 g_cbi[4][NC / 2];  // interleaved code-pair planes
__device__ float2 g_cni[NC / 2];     // norms per pair
__device__ ull   g_key[M];           // (monotone dist bits << 32) | tileId
__device__ int   g_idx[M];
__device__ float g_sums[NC * D];
__device__ float g_counts[NC];

__device__ __forceinline__ ull pack2(float lo, float hi) {
    ull r;
    asm("mov.b64 %0, {%1, %2};" : "=l"(r) : "f"(lo), "f"(hi));
    return r;
}
__device__ __forceinline__ void unpack2(ull v, float& lo, float& hi) {
    asm("mov.b64 {%0, %1}, %2;" : "=f"(lo), "=f"(hi) : "l"(v));
}
__device__ __forceinline__ void fma2(ull& d, ull a, ull b) {
    asm("fma.rn.f32x2 %0, %1, %2, %3;" : "=l"(d) : "l"(a), "l"(b), "l"(d));
}
__device__ __forceinline__ unsigned smem_u32(const void* p) {
    return (unsigned)__cvta_generic_to_shared(p);
}
__device__ __forceinline__ void cpa16(unsigned dst, const void* src) {
    asm volatile("cp.async.cg.shared.global [%0], [%1], 16;" :: "r"(dst), "l"(src));
}
__device__ __forceinline__ void cpa8(unsigned dst, const void* src) {
    asm volatile("cp.async.ca.shared.global [%0], [%1], 8;" :: "r"(dst), "l"(src));
}
__device__ __forceinline__ void cpa_commit() {
    asm volatile("cp.async.commit_group;");
}
template <int N>
__device__ __forceinline__ void cpa_wait() {
    asm volatile("cp.async.wait_group %0;" :: "n"(N));
}

// ---------------------------------------------------------------------------
// Fused prologue: zero sums/counts, init keys, interleave codebook, and
// (blocks 0..15) per-batch-row scale. Grid = (NC*D/256) blocks x 256 thr.
// ---------------------------------------------------------------------------
__global__ void k_pre(const float* __restrict__ x, const float* __restrict__ cb) {
    int t = blockIdx.x * blockDim.x + threadIdx.x;

    g_sums[t] = 0.f;                       // grid covers exactly NC*D
    if (t < NC) g_counts[t] = 0.f;
    if (t < M) g_key[t] = 0xFFFFFFFFFFFFFFFFull;

    if (t < NC / 2) {
        int p = t;
        const float4* cbv = (const float4*)cb;
        float4 a0 = cbv[4 * p + 0], a1 = cbv[4 * p + 1];  // code 2p
        float4 b0 = cbv[4 * p + 2], b1 = cbv[4 * p + 3];  // code 2p+1
        g_cbi[0][p] = make_float4(a0.x, b0.x, a0.y, b0.y);
        g_cbi[1][p] = make_float4(a0.z, b0.z, a0.w, b0.w);
        g_cbi[2][p] = make_float4(a1.x, b1.x, a1.y, b1.y);
        g_cbi[3][p] = make_float4(a1.z, b1.z, a1.w, b1.w);
        float na = a0.x * a0.x + a0.y * a0.y + a0.z * a0.z + a0.w * a0.w +
                   a1.x * a1.x + a1.y * a1.y + a1.z * a1.z + a1.w * a1.w;
        float nb = b0.x * b0.x + b0.y * b0.y + b0.z * b0.z + b0.w * b0.w +
                   b1.x * b1.x + b1.y * b1.y + b1.z * b1.z + b1.w * b1.w;
        g_cni[p] = make_float2(na, nb);
        g_cnorm[2 * p] = na;
        g_cnorm[2 * p + 1] = nb;
    }

    if (blockIdx.x < B_ROWS) {
        __shared__ float sh[256];
        const float* row = x + blockIdx.x * NCOL;
        float s = 0.f;
        for (int i = threadIdx.x; i < NCOL; i += blockDim.x) s += fabsf(row[i]);
        sh[threadIdx.x] = s;
        __syncthreads();
        for (int off = 128; off > 0; off >>= 1) {
            if (threadIdx.x < off) sh[threadIdx.x] += sh[threadIdx.x + off];
            __syncthreads();
        }
        if (threadIdx.x == 0) g_scale[blockIdx.x] = sh[0] * (1.0f / NCOL);
    }
}

// ---------------------------------------------------------------------------
// Pass 1: per-row min distance + winning 512-code tile. R=4 rows/thread,
// double-buffered cp.async staging, ONE barrier per tile:
//   wait(all groups) -> barrier -> commit prefetch(t+1) -> compute(t).
// The single barrier covers both cp.async visibility for tile t and the
// release of buffer b^1 by compute t-1 before the t+1 prefetch overwrites it.
// ---------------------------------------------------------------------------
__global__ void __launch_bounds__(256, 2) k_argmin(const float* __restrict__ x) {
    __shared__ float4 sh4[2][4][TILE2];   // 32 KB
    __shared__ float2 shcn[2][TILE2];     // 4 KB

    int row0 = blockIdx.x * ROWS_PER_BLOCK;
    int segBase = blockIdx.y * SEG_CODES;
    int ct = threadIdx.x & 31;
    int w = threadIdx.x >> 5;
    int myrow0 = row0 + w * R_PER_THREAD;
    int tid = threadIdx.x;

    // Duplicated (-2*x/scale) query pairs
    ull f2[R_PER_THREAD][D];
#pragma unroll
    for (int r = 0; r < R_PER_THREAD; r++) {
        int m = myrow0 + r;
        float c0 = -2.0f / g_scale[m / ROWS_PER_M];
        const float4* xr = (const float4*)(x + m * D);
        float4 a = xr[0], b = xr[1];
        f2[r][0] = pack2(a.x * c0, a.x * c0);
        f2[r][1] = pack2(a.y * c0, a.y * c0);
        f2[r][2] = pack2(a.z * c0, a.z * c0);
        f2[r][3] = pack2(a.w * c0, a.w * c0);
        f2[r][4] = pack2(b.x * c0, b.x * c0);
        f2[r][5] = pack2(b.y * c0, b.y * c0);
        f2[r][6] = pack2(b.z * c0, b.z * c0);
        f2[r][7] = pack2(b.w * c0, b.w * c0);
    }

    float bestV[R_PER_THREAD];
    int bestT[R_PER_THREAD];
#pragma unroll
    for (int r = 0; r < R_PER_THREAD; r++) { bestV[r] = 3.4e38f; bestT[r] = 0; }

    int pairBase0 = segBase >> 1;
    // Prologue: stage tile 0 into buffer 0
    {
#pragma unroll
        for (int rec = 0; rec < 4; rec++)
            cpa16(smem_u32(&sh4[0][rec][tid]), &g_cbi[rec][pairBase0 + tid]);
        cpa8(smem_u32(&shcn[0][tid]), &g_cni[pairBase0 + tid]);
        cpa_commit();
    }

    for (int t = 0; t < NTILES; t++) {
        int b = t & 1;
        cpa_wait<0>();        // tile t data has landed (only group in flight)
        __syncthreads();      // visibility + buffer b^1 released by compute t-1

        if (t + 1 < NTILES) { // prefetch t+1 into the just-released buffer
            int pb = pairBase0 + (t + 1) * TILE2;
#pragma unroll
            for (int rec = 0; rec < 4; rec++)
                cpa16(smem_u32(&sh4[b ^ 1][rec][tid]), &g_cbi[rec][pb + tid]);
            cpa8(smem_u32(&shcn[b ^ 1][tid]), &g_cni[pb + tid]);
            cpa_commit();
        }

        float pl[R_PER_THREAD], ph[R_PER_THREAD];
#pragma unroll
        for (int r = 0; r < R_PER_THREAD; r++) { pl[r] = 3.4e38f; ph[r] = 3.4e38f; }

#pragma unroll 4
        for (int i = 0; i < TILE2 / 32; i++) {
            int c2 = ct + 32 * i;
            ulonglong2 q0 = *(const ulonglong2*)&sh4[b][0][c2];
            ulonglong2 q1 = *(const ulonglong2*)&sh4[b][1][c2];
            ulonglong2 q2 = *(const ulonglong2*)&sh4[b][2][c2];
            ulonglong2 q3 = *(const ulonglong2*)&sh4[b][3][c2];
            ull cn2 = *(const ull*)&shcn[b][c2];
#pragma unroll
            for (int r = 0; r < R_PER_THREAD; r++) {
                ull d = cn2;
                fma2(d, f2[r][0], q0.x);
                fma2(d, f2[r][1], q0.y);
                fma2(d, f2[r][2], q1.x);
                fma2(d, f2[r][3], q1.y);
                fma2(d, f2[r][4], q2.x);
                fma2(d, f2[r][5], q2.y);
                fma2(d, f2[r][6], q3.x);
                fma2(d, f2[r][7], q3.y);
                float de, dodd;
                unpack2(d, de, dodd);
                pl[r] = fminf(pl[r], de);
                ph[r] = fminf(ph[r], dodd);
            }
        }

        int tileId = (segBase >> 9) + t;
#pragma unroll
        for (int r = 0; r < R_PER_THREAD; r++) {
            float tmin = fminf(pl[r], ph[r]);
            if (tmin < bestV[r]) { bestV[r] = tmin; bestT[r] = tileId; }
        }
    }

    // Warp reduce lexicographic (val, tile) across 32 code lanes
#pragma unroll
    for (int r = 0; r < R_PER_THREAD; r++) {
        float d = bestV[r];
        int t = bestT[r];
        for (int off = 16; off > 0; off >>= 1) {
            float d2 = __shfl_down_sync(0xffffffffu, d, off);
            int t2 = __shfl_down_sync(0xffffffffu, t, off);
            if (d2 < d || (d2 == d && t2 < t)) { d = d2; t = t2; }
        }
        if (ct == 0) {
            unsigned int ud = __float_as_uint(d);
            ud = (ud & 0x80000000u) ? ~ud : (ud | 0x80000000u);
            ull key = ((ull)ud << 32) | (unsigned int)t;
            atomicMin(&g_key[myrow0 + r], key);
        }
    }
}

// ---------------------------------------------------------------------------
// Pass 2 (fused resolve + scatter): one warp per row rescans its winning
// tile with the bit-identical fma2 chain; first matching index wins
// (jnp.argmin first-index semantics). Then the warp scatters count + sums.
// ---------------------------------------------------------------------------
__global__ void __launch_bounds__(256) k_resolve(const float* __restrict__ x,
                                                 const float* __restrict__ cb) {
    int m = blockIdx.x * (blockDim.x >> 5) + (threadIdx.x >> 5);
    int lane = threadIdx.x & 31;
    if (m >= M) return;

    ull key = g_key[m];
    int tile = (int)(key & 0xFFFFFFFFu);
    unsigned int ud = (unsigned int)(key >> 32);
    ud = (ud & 0x80000000u) ? (ud & 0x7FFFFFFFu) : ~ud;  // inverse monotone map
    float target = __uint_as_float(ud);

    float inv = 1.0f / g_scale[m / ROWS_PER_M];
    float c0 = -2.0f * inv;
    const float4* xr = (const float4*)(x + m * D);
    float4 a = xr[0], b = xr[1];
    ull f2r[D];
    f2r[0] = pack2(a.x * c0, a.x * c0);
    f2r[1] = pack2(a.y * c0, a.y * c0);
    f2r[2] = pack2(a.z * c0, a.z * c0);
    f2r[3] = pack2(a.w * c0, a.w * c0);
    f2r[4] = pack2(b.x * c0, b.x * c0);
    f2r[5] = pack2(b.y * c0, b.y * c0);
    f2r[6] = pack2(b.z * c0, b.z * c0);
    f2r[7] = pack2(b.w * c0, b.w * c0);

    const float4* cbv = (const float4*)cb;
    int base = tile * TILE;
    int best = 0x7FFFFFFF;

#pragma unroll
    for (int p = 0; p < TILE2 / 32; p++) {
        int c2 = lane + 32 * p;
        int code0 = base + 2 * c2;
        float4 a0 = cbv[code0 * 2 + 0];
        float4 a1 = cbv[code0 * 2 + 1];
        float4 b0 = cbv[code0 * 2 + 2];
        float4 b1 = cbv[code0 * 2 + 3];
        ull d = pack2(g_cnorm[code0], g_cnorm[code0 + 1]);
        fma2(d, f2r[0], pack2(a0.x, b0.x));
        fma2(d, f2r[1], pack2(a0.y, b0.y));
        fma2(d, f2r[2], pack2(a0.z, b0.z));
        fma2(d, f2r[3], pack2(a0.w, b0.w));
        fma2(d, f2r[4], pack2(a1.x, b1.x));
        fma2(d, f2r[5], pack2(a1.y, b1.y));
        fma2(d, f2r[6], pack2(a1.z, b1.z));
        fma2(d, f2r[7], pack2(a1.w, b1.w));
        float de, dodd;
        unpack2(d, de, dodd);
        if (de == target) best = min(best, code0);
        else if (dodd == target) best = min(best, code0 + 1);
    }

    // Butterfly reduce so ALL lanes hold the winning index
    for (int off = 16; off > 0; off >>= 1)
        best = min(best, __shfl_xor_sync(0xffffffffu, best, off));

    if (lane == 0) {
        g_idx[m] = best;
        atomicAdd(&g_counts[best], 1.f);
    }
    if (lane < D) {
        float v = x[m * D + lane] * inv;
        atomicAdd(&g_sums[best * D + lane], v);
    }
}

// ---------------------------------------------------------------------------
__global__ void k_gather(float* __restrict__ out) {
    int t = blockIdx.x * blockDim.x + threadIdx.x;
    if (t >= M * D) return;
    int m = t >> 3;
    int j = t & 7;
    int idx = g_idx[m];
    float cnt = g_counts[idx];
    cnt = cnt < 1.f ? 1.f : cnt;
    out[t] = g_scale[m / ROWS_PER_M] * (g_sums[idx * D + j] / cnt);
}

// ---------------------------------------------------------------------------
extern "C" void kernel_launch(void* const* d_in, const int* in_sizes, int n_in,
                              void* d_out, int out_size) {
    const float* x = (const float*)d_in[0];
    const float* cb = (const float*)d_in[1];
    if (n_in >= 2 && in_sizes[0] > in_sizes[1]) {
        x = (const float*)d_in[1];
        cb = (const float*)d_in[0];
    }
    float* out = (float*)d_out;

    k_pre<<<(NC * D) / 256, 256>>>(x, cb);
    dim3 grid(M / ROWS_PER_BLOCK, NSEG);
    k_argmin<<<grid, 256>>>(x);
    k_resolve<<<M / 8, 256>>>(x, cb);
    k_gather<<<(M * D) / 256, 256>>>(out);
}

// round 9
// speedup vs baseline: 1.4225x; 1.0163x over previous
#include <cuda_runtime.h>

// Problem constants
#define B_ROWS 16
#define NCOL 2048
#define M 4096          // flat rows
#define D 8
#define NC 65536
#define ROWS_PER_M 256  // flat rows per batch row

// Argmin tunables: 8 rows/thread (4 packed row-pairs), codes walked scalar
#define ROWS_PER_THREAD 8
#define RP 4                                     // row-pairs
#define NWARPS 8
#define ROWS_PER_BLOCK (NWARPS * ROWS_PER_THREAD)  // 64
#define NSEG 16
#define SEG_CODES (NC / NSEG)                    // 4096
#define TILE 512                                 // codes per shared tile
#define NTILES (SEG_CODES / TILE)                // 8

typedef unsigned long long ull;

// Scratch
__device__ float g_scale[B_ROWS];
__device__ float g_cnorm[NC];
__device__ float g_planes[9][NC];    // dim-major planes (8 dims + norm)
__device__ ull   g_key[M];           // (monotone dist bits << 32) | tileId
__device__ int   g_idx[M];
__device__ float g_sums[NC * D];
__device__ float g_counts[NC];

__device__ __forceinline__ ull pack2(float lo, float hi) {
    ull r;
    asm("mov.b64 %0, {%1, %2};" : "=l"(r) : "f"(lo), "f"(hi));
    return r;
}
__device__ __forceinline__ void unpack2(ull v, float& lo, float& hi) {
    asm("mov.b64 {%0, %1}, %2;" : "=f"(lo), "=f"(hi) : "l"(v));
}
__device__ __forceinline__ void fma2(ull& d, ull a, ull b) {
    asm("fma.rn.f32x2 %0, %1, %2, %3;" : "=l"(d) : "l"(a), "l"(b), "l"(d));
}
__device__ __forceinline__ unsigned smem_u32(const void* p) {
    return (unsigned)__cvta_generic_to_shared(p);
}
__device__ __forceinline__ void cpa16(unsigned dst, const void* src) {
    asm volatile("cp.async.cg.shared.global [%0], [%1], 16;" :: "r"(dst), "l"(src));
}
__device__ __forceinline__ void cpa_commit() {
    asm volatile("cp.async.commit_group;");
}
template <int N>
__device__ __forceinline__ void cpa_wait() {
    asm volatile("cp.async.wait_group %0;" :: "n"(N));
}

// ---------------------------------------------------------------------------
// Fused prologue: zero sums/counts, init keys, build dim-major planes +
// norms, and (blocks 0..15) per-batch-row scale.
// ---------------------------------------------------------------------------
__global__ void k_pre(const float* __restrict__ x, const float* __restrict__ cb) {
    int t = blockIdx.x * blockDim.x + threadIdx.x;

    g_sums[t] = 0.f;                       // grid covers exactly NC*D
    if (t < NC) g_counts[t] = 0.f;
    if (t < M) g_key[t] = 0xFFFFFFFFFFFFFFFFull;

    if (t < NC) {                          // build planes for code t
        const float4* cbv = (const float4*)cb;
        float4 a = cbv[2 * t], b = cbv[2 * t + 1];
        g_planes[0][t] = a.x;
        g_planes[1][t] = a.y;
        g_planes[2][t] = a.z;
        g_planes[3][t] = a.w;
        g_planes[4][t] = b.x;
        g_planes[5][t] = b.y;
        g_planes[6][t] = b.z;
        g_planes[7][t] = b.w;
        float n = a.x * a.x + a.y * a.y + a.z * a.z + a.w * a.w +
                  b.x * b.x + b.y * b.y + b.z * b.z + b.w * b.w;
        g_planes[8][t] = n;
        g_cnorm[t] = n;
    }

    if (blockIdx.x < B_ROWS) {
        __shared__ float sh[256];
        const float* row = x + blockIdx.x * NCOL;
        float s = 0.f;
        for (int i = threadIdx.x; i < NCOL; i += blockDim.x) s += fabsf(row[i]);
        sh[threadIdx.x] = s;
        __syncthreads();
        for (int off = 128; off > 0; off >>= 1) {
            if (threadIdx.x < off) sh[threadIdx.x] += sh[threadIdx.x + off];
            __syncthreads();
        }
        if (threadIdx.x == 0) g_scale[blockIdx.x] = sh[0] * (1.0f / NCOL);
    }
}

// ---------------------------------------------------------------------------
// Pass 1: per-row min distance + winning 512-code tile.
// Two ROWS ride the f32x2 lanes; codes are walked scalar from dim-major
// shared planes (9 x 4B per code, conflict-free broadcast-free stride).
// Per code: 9 LDS + 9 dup movs + 32 FFMA2 + 4 unpack + 8 FMNMX serving
// 64 scalar FMAs (0.56 B-of-LDS/FMA). Double-buffered cp.async staging,
// one barrier per tile.
// ---------------------------------------------------------------------------
__global__ void __launch_bounds__(256, 2) k_argmin(const float* __restrict__ x) {
    __shared__ float shp[2][9][TILE];   // 36 KB

    int row0 = blockIdx.x * ROWS_PER_BLOCK;
    int segBase = blockIdx.y * SEG_CODES;
    int ct = threadIdx.x & 31;
    int w = threadIdx.x >> 5;
    int myrow0 = row0 + w * ROWS_PER_THREAD;
    int tid = threadIdx.x;

    // Queries: 4 row-pairs x 8 dims, packed (f_even[j], f_odd[j]) * (-2/scale)
    ull f2[RP][D];
#pragma unroll
    for (int rp = 0; rp < RP; rp++) {
        int m0 = myrow0 + 2 * rp;
        float s0 = -2.0f / g_scale[m0 / ROWS_PER_M];
        float s1 = -2.0f / g_scale[(m0 + 1) / ROWS_PER_M];
        const float4* x0 = (const float4*)(x + m0 * D);
        const float4* x1 = (const float4*)(x + (m0 + 1) * D);
        float4 a0 = x0[0], b0 = x0[1];
        float4 a1 = x1[0], b1 = x1[1];
        f2[rp][0] = pack2(a0.x * s0, a1.x * s1);
        f2[rp][1] = pack2(a0.y * s0, a1.y * s1);
        f2[rp][2] = pack2(a0.z * s0, a1.z * s1);
        f2[rp][3] = pack2(a0.w * s0, a1.w * s1);
        f2[rp][4] = pack2(b0.x * s0, b1.x * s1);
        f2[rp][5] = pack2(b0.y * s0, b1.y * s1);
        f2[rp][6] = pack2(b0.z * s0, b1.z * s1);
        f2[rp][7] = pack2(b0.w * s0, b1.w * s1);
    }

    float bestV[ROWS_PER_THREAD];
    int bestT[ROWS_PER_THREAD];
#pragma unroll
    for (int r = 0; r < ROWS_PER_THREAD; r++) { bestV[r] = 3.4e38f; bestT[r] = 0; }

    // Prologue: stage tile 0 into buffer 0 (9 planes x 128 float4 = 1152 tasks)
#pragma unroll
    for (int q = tid; q < 9 * (TILE / 4); q += 256) {
        int j = q >> 7;
        int c4 = q & 127;
        cpa16(smem_u32(&shp[0][j][c4 * 4]), &g_planes[j][segBase + c4 * 4]);
    }
    cpa_commit();

    for (int t = 0; t < NTILES; t++) {
        int b = t & 1;
        cpa_wait<0>();        // tile t landed (only group in flight)
        __syncthreads();      // visibility + buffer b^1 released by compute t-1

        if (t + 1 < NTILES) {
            int base = segBase + (t + 1) * TILE;
#pragma unroll
            for (int q = tid; q < 9 * (TILE / 4); q += 256) {
                int j = q >> 7;
                int c4 = q & 127;
                cpa16(smem_u32(&shp[b ^ 1][j][c4 * 4]), &g_planes[j][base + c4 * 4]);
            }
            cpa_commit();
        }

        // Per-tile mins: scalar accumulators per row (even/odd lanes)
        float pl[RP], ph[RP];
#pragma unroll
        for (int rp = 0; rp < RP; rp++) { pl[rp] = 3.4e38f; ph[rp] = 3.4e38f; }

#pragma unroll 4
        for (int i = 0; i < TILE / 32; i++) {
            int c = ct + 32 * i;
            float v0 = shp[b][0][c];
            float v1 = shp[b][1][c];
            float v2 = shp[b][2][c];
            float v3 = shp[b][3][c];
            float v4 = shp[b][4][c];
            float v5 = shp[b][5][c];
            float v6 = shp[b][6][c];
            float v7 = shp[b][7][c];
            float vn = shp[b][8][c];
            ull q0 = pack2(v0, v0);
            ull q1 = pack2(v1, v1);
            ull q2 = pack2(v2, v2);
            ull q3 = pack2(v3, v3);
            ull q4 = pack2(v4, v4);
            ull q5 = pack2(v5, v5);
            ull q6 = pack2(v6, v6);
            ull q7 = pack2(v7, v7);
            ull qn = pack2(vn, vn);
#pragma unroll
            for (int rp = 0; rp < RP; rp++) {
                ull d = qn;
                fma2(d, f2[rp][0], q0);
                fma2(d, f2[rp][1], q1);
                fma2(d, f2[rp][2], q2);
                fma2(d, f2[rp][3], q3);
                fma2(d, f2[rp][4], q4);
                fma2(d, f2[rp][5], q5);
                fma2(d, f2[rp][6], q6);
                fma2(d, f2[rp][7], q7);
                float de, dodd;
                unpack2(d, de, dodd);
                pl[rp] = fminf(pl[rp], de);
                ph[rp] = fminf(ph[rp], dodd);
            }
        }

        int tileId = (segBase >> 9) + t;
#pragma unroll
        for (int rp = 0; rp < RP; rp++) {
            if (pl[rp] < bestV[2 * rp]) { bestV[2 * rp] = pl[rp]; bestT[2 * rp] = tileId; }
            if (ph[rp] < bestV[2 * rp + 1]) { bestV[2 * rp + 1] = ph[rp]; bestT[2 * rp + 1] = tileId; }
        }
    }

    // Warp reduce lexicographic (val, tile) across the 32 code lanes
#pragma unroll
    for (int r = 0; r < ROWS_PER_THREAD; r++) {
        float d = bestV[r];
        int t = bestT[r];
        for (int off = 16; off > 0; off >>= 1) {
            float d2 = __shfl_down_sync(0xffffffffu, d, off);
            int t2 = __shfl_down_sync(0xffffffffu, t, off);
            if (d2 < d || (d2 == d && t2 < t)) { d = d2; t = t2; }
        }
        if (ct == 0) {
            unsigned int ud = __float_as_uint(d);
            ud = (ud & 0x80000000u) ? ~ud : (ud | 0x80000000u);
            ull key = ((ull)ud << 32) | (unsigned int)t;
            atomicMin(&g_key[myrow0 + r], key);
        }
    }
}

// ---------------------------------------------------------------------------
// Pass 2 (fused resolve + scatter): one warp per row rescans its winning
// tile. Distances recomputed with an fma2 chain using IDENTICAL operand
// values and op order as pass 1 (norm seed, dims 0..7) -> bit-identical;
// first matching index wins (jnp.argmin first-index semantics).
// ---------------------------------------------------------------------------
__global__ void __launch_bounds__(256) k_resolve(const float* __restrict__ x,
                                                 const float* __restrict__ cb) {
    int m = blockIdx.x * (blockDim.x >> 5) + (threadIdx.x >> 5);
    int lane = threadIdx.x & 31;
    if (m >= M) return;

    ull key = g_key[m];
    int tile = (int)(key & 0xFFFFFFFFu);
    unsigned int ud = (unsigned int)(key >> 32);
    ud = (ud & 0x80000000u) ? (ud & 0x7FFFFFFFu) : ~ud;  // inverse monotone map
    float target = __uint_as_float(ud);

    float inv = 1.0f / g_scale[m / ROWS_PER_M];
    float c0 = -2.0f * inv;
    const float4* xr = (const float4*)(x + m * D);
    float4 a = xr[0], b = xr[1];
    ull f2r[D];
    f2r[0] = pack2(a.x * c0, a.x * c0);
    f2r[1] = pack2(a.y * c0, a.y * c0);
    f2r[2] = pack2(a.z * c0, a.z * c0);
    f2r[3] = pack2(a.w * c0, a.w * c0);
    f2r[4] = pack2(b.x * c0, b.x * c0);
    f2r[5] = pack2(b.y * c0, b.y * c0);
    f2r[6] = pack2(b.z * c0, b.z * c0);
    f2r[7] = pack2(b.w * c0, b.w * c0);

    const float4* cbv = (const float4*)cb;
    int base = tile * TILE;
    int best = 0x7FFFFFFF;

#pragma unroll
    for (int p = 0; p < TILE / 2 / 32; p++) {
        int c2 = lane + 32 * p;
        int code0 = base + 2 * c2;
        float4 a0 = cbv[code0 * 2 + 0];
        float4 a1 = cbv[code0 * 2 + 1];
        float4 b0 = cbv[code0 * 2 + 2];
        float4 b1 = cbv[code0 * 2 + 3];
        ull d = pack2(g_cnorm[code0], g_cnorm[code0 + 1]);
        fma2(d, f2r[0], pack2(a0.x, b0.x));
        fma2(d, f2r[1], pack2(a0.y, b0.y));
        fma2(d, f2r[2], pack2(a0.z, b0.z));
        fma2(d, f2r[3], pack2(a0.w, b0.w));
        fma2(d, f2r[4], pack2(a1.x, b1.x));
        fma2(d, f2r[5], pack2(a1.y, b1.y));
        fma2(d, f2r[6], pack2(a1.z, b1.z));
        fma2(d, f2r[7], pack2(a1.w, b1.w));
        float de, dodd;
        unpack2(d, de, dodd);
        if (de == target) best = min(best, code0);
        else if (dodd == target) best = min(best, code0 + 1);
    }

    // Butterfly reduce so ALL lanes hold the winning index
    for (int off = 16; off > 0; off >>= 1)
        best = min(best, __shfl_xor_sync(0xffffffffu, best, off));

    if (lane == 0) {
        g_idx[m] = best;
        atomicAdd(&g_counts[best], 1.f);
    }
    if (lane < D) {
        float v = x[m * D + lane] * inv;
        atomicAdd(&g_sums[best * D + lane], v);
    }
}

// ---------------------------------------------------------------------------
__global__ void k_gather(float* __restrict__ out) {
    int t = blockIdx.x * blockDim.x + threadIdx.x;
    if (t >= M * D) return;
    int m = t >> 3;
    int j = t & 7;
    int idx = g_idx[m];
    float cnt = g_counts[idx];
    cnt = cnt < 1.f ? 1.f : cnt;
    out[t] = g_scale[m / ROWS_PER_M] * (g_sums[idx * D + j] / cnt);
}

// ---------------------------------------------------------------------------
extern "C" void kernel_launch(void* const* d_in, const int* in_sizes, int n_in,
                              void* d_out, int out_size) {
    const float* x = (const float*)d_in[0];
    const float* cb = (const float*)d_in[1];
    if (n_in >= 2 && in_sizes[0] > in_sizes[1]) {
        x = (const float*)d_in[1];
        cb = (const float*)d_in[0];
    }
    float* out = (float*)d_out;

    k_pre<<<(NC * D) / 256, 256>>>(x, cb);
    dim3 grid(M / ROWS_PER_BLOCK, NSEG);
    k_argmin<<<grid, 256>>>(x);
    k_resolve<<<M / 8, 256>>>(x, cb);
    k_gather<<<(M * D) / 256, 256>>>(out);
}